// round 9
// baseline (speedup 1.0000x reference)
#include <cuda_runtime.h>
#include <cuda_fp16.h>
#include <cstdint>

#define D_DIM   512
#define K_DIM   112
#define BM      128
#define NTHR    256
#define NIT     16               // k-chunks of 32
#define LAMBDA_ 5.0f

// SMEM: two A stages (hi+lo), sims overlays afterwards
#define A_STRIDE   80                        // bytes per 32-fp16 row (64 data + 16 pad)
#define A_HALF     (BM * A_STRIDE)           // 10240
#define STAGE_B    (2 * A_HALF)              // 20480 (AH + AL)
#define SIMSP      114
#define SIMS_B     (BM * SIMSP * 4)          // 58368
#define W5_OFF     SIMS_B
#define I5_OFF     (W5_OFF + BM * 5 * 4)
#define SMEM_BYTES (I5_OFF + BM * 5 * 4)     // 63488

// B fragment buffers: [kh(32)][n8(14)][lane(32)] x uint2 {b0,b1}
#define FRAG_U2    (32 * 14 * 32)
__device__ __align__(16) uint2 g_bh[FRAG_U2];
__device__ __align__(16) uint2 g_bl[FRAG_U2];

__device__ __forceinline__ uint32_t smem_u32(const void* p) {
    uint32_t a;
    asm("{ .reg .u64 t; cvta.to.shared.u64 t, %1; cvt.u32.u64 %0, t; }" : "=r"(a) : "l"(p));
    return a;
}
__device__ __forceinline__ void splith(float a, float b, uint32_t& hi, uint32_t& lo) {
    __half2 h = __floats2half2_rn(a, b);
    float2  f = __half22float2(h);
    __half2 l = __floats2half2_rn(a - f.x, b - f.y);
    hi = *(uint32_t*)&h;
    lo = *(uint32_t*)&l;
}

#define LDSM4(r, addr) \
    asm volatile("ldmatrix.sync.aligned.m8n8.x4.shared.b16 {%0,%1,%2,%3}, [%4];" \
                 : "=r"((r)[0]), "=r"((r)[1]), "=r"((r)[2]), "=r"((r)[3]) : "r"(addr))

#define MMA(d, a, b0, b1) \
    asm volatile("mma.sync.aligned.m16n8k16.row.col.f32.f16.f16.f32 " \
                 "{%0,%1,%2,%3}, {%4,%5,%6,%7}, {%8,%9}, {%0,%1,%2,%3};" \
                 : "+f"((d)[0]), "+f"((d)[1]), "+f"((d)[2]), "+f"((d)[3]) \
                 : "r"((a)[0]), "r"((a)[1]), "r"((a)[2]), "r"((a)[3]), "r"(b0), "r"(b1))

// ---- pre-kernel: bake C into per-n8-tile mma B fragments (hi/lo fp16) ----
__global__ void cc_frag_kernel(const float* __restrict__ cc) {
    int kh = blockIdx.x / 14, n8 = blockIdx.x % 14;
    int l = threadIdx.x;
    int n  = n8 * 8 + (l >> 2);
    int k0 = kh * 16 + (l & 3) * 2;
    uint32_t b0h, b0l, b1h, b1l;
    splith(cc[n * D_DIM + k0],     cc[n * D_DIM + k0 + 1], b0h, b0l);
    splith(cc[n * D_DIM + k0 + 8], cc[n * D_DIM + k0 + 9], b1h, b1l);
    g_bh[blockIdx.x * 32 + l] = make_uint2(b0h, b1h);
    g_bl[blockIdx.x * 32 + l] = make_uint2(b0l, b1l);
}

__global__ __launch_bounds__(NTHR, 2)
void tse_hmma3_kernel(const float* __restrict__ x,
                      const float* __restrict__ cc,
                      float* __restrict__ out)
{
    extern __shared__ unsigned char smem[];
    const uint32_t sb = smem_u32(smem);
    const int tid = threadIdx.x;
    const int w   = tid >> 5;
    const int l   = tid & 31;
    const int mg  = w & 3;          // m-group: rows mg*32 .. mg*32+31
    const int nh  = w >> 2;         // n-half: cols nh*56 .. nh*56+55
    const int nb7 = nh * 7;         // first n8-tile index
    const int row0 = blockIdx.x * BM;

    float d[2][7][4];
    #pragma unroll
    for (int m = 0; m < 2; m++)
        #pragma unroll
        for (int p = 0; p < 7; p++)
            #pragma unroll
            for (int j = 0; j < 4; j++) d[m][p][j] = 0.0f;

    // ldmatrix A base offsets (within a stage): row = mg*32 + mh*16 + (l&15)
    const uint32_t aOff = (uint32_t)(mg * 32 + (l & 15)) * A_STRIDE + ((l >> 4) << 4);

    // x staging: 4 float4 per thread per iteration
    const int srow0 = tid >> 3;
    const int sseg  = tid & 7;
    float4 px[4];

    auto FETCH = [&](int it) {
        #pragma unroll
        for (int i = 0; i < 4; i++)
            px[i] = *(const float4*)&x[(size_t)(row0 + srow0 + 32 * i) * D_DIM + it * 32 + sseg * 4];
    };
    auto STORE = [&](int s) {
        unsigned char* st = smem + s * STAGE_B;
        #pragma unroll
        for (int i = 0; i < 4; i++) {
            uint32_t h0, l0, h1, l1;
            splith(px[i].x, px[i].y, h0, l0);
            splith(px[i].z, px[i].w, h1, l1);
            uint32_t off = (uint32_t)(srow0 + 32 * i) * A_STRIDE + sseg * 8;
            *(uint2*)(st + off)          = make_uint2(h0, h1);
            *(uint2*)(st + A_HALF + off) = make_uint2(l0, l1);
        }
    };

    const uint2* __restrict__ BH = g_bh;
    const uint2* __restrict__ BL = g_bl;

    FETCH(0);
    STORE(0);
    __syncthreads();

    for (int it = 0; it < NIT; it++) {
        if (it + 1 < NIT) FETCH(it + 1);           // LDG latency covered by MMAs below

        const uint32_t aBase = sb + (it & 1) * STAGE_B + aOff;
        #pragma unroll
        for (int h = 0; h < 2; h++) {
            const int kh = it * 2 + h;
            uint32_t ah[2][4], al[2][4];
            LDSM4(ah[0], aBase + h * 32);
            LDSM4(ah[1], aBase + 16 * A_STRIDE + h * 32);
            LDSM4(al[0], aBase + A_HALF + h * 32);
            LDSM4(al[1], aBase + A_HALF + 16 * A_STRIDE + h * 32);

            uint2 b[7];
            #pragma unroll
            for (int p = 0; p < 7; p++)
                b[p] = BH[(kh * 14 + nb7 + p) * 32 + l];
            #pragma unroll
            for (int p = 0; p < 7; p++) {
                MMA(d[0][p], ah[0], b[p].x, b[p].y);
                MMA(d[1][p], ah[1], b[p].x, b[p].y);
                MMA(d[0][p], al[0], b[p].x, b[p].y);
                MMA(d[1][p], al[1], b[p].x, b[p].y);
            }
            #pragma unroll
            for (int p = 0; p < 7; p++)
                b[p] = BL[(kh * 14 + nb7 + p) * 32 + l];
            #pragma unroll
            for (int p = 0; p < 7; p++) {
                MMA(d[0][p], ah[0], b[p].x, b[p].y);
                MMA(d[1][p], ah[1], b[p].x, b[p].y);
            }
        }

        if (it + 1 < NIT) STORE((it + 1) & 1);     // writes the other stage
        __syncthreads();
    }

    // ---- dump sims to smem (overlays A stages) ----
    float* sims = (float*)smem;
    {
        int c0 = nh * 56 + (l & 3) * 2;
        #pragma unroll
        for (int m = 0; m < 2; m++) {
            int r1 = mg * 32 + m * 16 + (l >> 2);
            int r2 = r1 + 8;
            #pragma unroll
            for (int p = 0; p < 7; p++) {
                *(float2*)&sims[r1 * SIMSP + c0 + p * 8] = make_float2(d[m][p][0], d[m][p][1]);
                *(float2*)&sims[r2 * SIMSP + c0 + p * 8] = make_float2(d[m][p][2], d[m][p][3]);
            }
        }
    }
    __syncthreads();

    // ---- per-row top-5 + softmax ----
    float* w5 = (float*)(smem + W5_OFF);
    int*   i5 = (int*)(smem + I5_OFF);
    if (tid < BM) {
        const float* sr = &sims[tid * SIMSP];
        float v0 = -1e30f, v1 = -1e30f, v2 = -1e30f, v3 = -1e30f, v4 = -1e30f;
        int   i0 = 0, i1 = 0, i2 = 0, i3 = 0, i4 = 0;
        for (int c = 0; c < K_DIM; c++) {
            float s = sr[c];
            if (s > v4) {                       // strict >: earliest index wins ties
                v4 = s; i4 = c;
                if (v4 > v3) { float t=v3; v3=v4; v4=t; int q=i3; i3=i4; i4=q; }
                if (v3 > v2) { float t=v2; v2=v3; v3=t; int q=i2; i2=i3; i3=q; }
                if (v2 > v1) { float t=v1; v1=v2; v2=t; int q=i1; i1=i2; i2=q; }
                if (v1 > v0) { float t=v0; v0=v1; v1=t; int q=i0; i0=i1; i1=q; }
            }
        }
        float e1 = __expf(v1 - v0);
        float e2 = __expf(v2 - v0);
        float e3 = __expf(v3 - v0);
        float e4 = __expf(v4 - v0);
        float inv = LAMBDA_ / (1.0f + e1 + e2 + e3 + e4);
        w5[tid*5+0] = inv;      i5[tid*5+0] = i0;
        w5[tid*5+1] = e1 * inv; i5[tid*5+1] = i1;
        w5[tid*5+2] = e2 * inv; i5[tid*5+2] = i2;
        w5[tid*5+3] = e3 * inv; i5[tid*5+3] = i3;
        w5[tid*5+4] = e4 * inv; i5[tid*5+4] = i4;
    }
    __syncthreads();

    // ---- epilogue: warp-per-row, fully coalesced ----
    #pragma unroll 1
    for (int rr = 0; rr < 16; rr++) {
        int r = w * 16 + rr;
        float w0 = w5[r*5+0], w1 = w5[r*5+1], w2 = w5[r*5+2], w3 = w5[r*5+3], w4 = w5[r*5+4];
        int   j0 = i5[r*5+0], j1 = i5[r*5+1], j2 = i5[r*5+2], j3 = i5[r*5+3], j4 = i5[r*5+4];

        const float4* xp = (const float4*)&x[(size_t)(row0 + r) * D_DIM];
        float4*       op = (float4*)&out[(size_t)(row0 + r) * D_DIM];
        const float4* c0 = (const float4*)&cc[(size_t)j0 * D_DIM];
        const float4* c1 = (const float4*)&cc[(size_t)j1 * D_DIM];
        const float4* c2 = (const float4*)&cc[(size_t)j2 * D_DIM];
        const float4* c3 = (const float4*)&cc[(size_t)j3 * D_DIM];
        const float4* c4 = (const float4*)&cc[(size_t)j4 * D_DIM];

        #pragma unroll
        for (int i = 0; i < 4; i++) {
            int q = l + 32 * i;
            float4 xv = xp[q];
            float4 a0 = c0[q], a1 = c1[q], a2 = c2[q], a3 = c3[q], a4 = c4[q];
            float4 o;
            o.x = xv.x + w0*a0.x + w1*a1.x + w2*a2.x + w3*a3.x + w4*a4.x;
            o.y = xv.y + w0*a0.y + w1*a1.y + w2*a2.y + w3*a3.y + w4*a4.y;
            o.z = xv.z + w0*a0.z + w1*a1.z + w2*a2.z + w3*a3.z + w4*a4.z;
            o.w = xv.w + w0*a0.w + w1*a1.w + w2*a2.w + w3*a3.w + w4*a4.w;
            op[q] = o;
        }
    }
}

extern "C" void kernel_launch(void* const* d_in, const int* in_sizes, int n_in,
                              void* d_out, int out_size)
{
    const float* x  = (const float*)d_in[0];
    const float* cc = (const float*)d_in[1];
    int B = in_sizes[0] / D_DIM;

    cc_frag_kernel<<<32 * 14, 32>>>(cc);

    cudaFuncSetAttribute(tse_hmma3_kernel, cudaFuncAttributeMaxDynamicSharedMemorySize, SMEM_BYTES);
    tse_hmma3_kernel<<<B / BM, NTHR, SMEM_BYTES>>>(x, cc, (float*)d_out);
}

// round 10
// speedup vs baseline: 1.5039x; 1.5039x over previous
#include <cuda_runtime.h>
#include <cuda_fp16.h>
#include <cstdint>

#define D_DIM   512
#define K_DIM   112
#define BM      128
#define NTHR    256
#define NIT     16               // k-chunks of 32
#define LAMBDA_ 5.0f

// SMEM layout (bytes)
#define A_STRIDE   80                        // 32 fp16 + 16B pad per row
#define A_HALF     (BM * A_STRIDE)           // 10240
#define A_STAGE    (2 * A_HALF)              // 20480 (hi + lo)
#define B_OFF      (2 * A_STAGE)             // 40960
#define B_STAGE    14336                     // per-it B fragments (2 kh x 2 hl x 14 x 32 x 8B)
#define SMEM_BYTES (B_OFF + 2 * B_STAGE)     // 69632
// sims/top-k overlay the GEMM buffers after the mainloop
#define SIMSP      114
#define W5_OFF     (BM * SIMSP * 4)          // 58368
#define I5_OFF     (W5_OFF + BM * 5 * 4)     // 60928  (ends 63488 < 69632)

// B fragments baked in mma order: [kh(32)][hl(2)][tile(14)][lane(32)] x uint2{b0,b1}
__device__ __align__(16) uint2 g_bfrag[32 * 2 * 14 * 32];

__device__ __forceinline__ uint32_t smem_u32(const void* p) {
    uint32_t a;
    asm("{ .reg .u64 t; cvta.to.shared.u64 t, %1; cvt.u32.u64 %0, t; }" : "=r"(a) : "l"(p));
    return a;
}
__device__ __forceinline__ void splith(float a, float b, uint32_t& hi, uint32_t& lo) {
    __half2 h = __floats2half2_rn(a, b);
    float2  f = __half22float2(h);
    __half2 l = __floats2half2_rn(a - f.x, b - f.y);
    hi = *(uint32_t*)&h;
    lo = *(uint32_t*)&l;
}

#define LDSM4(r, addr) \
    asm volatile("ldmatrix.sync.aligned.m8n8.x4.shared.b16 {%0,%1,%2,%3}, [%4];" \
                 : "=r"((r)[0]), "=r"((r)[1]), "=r"((r)[2]), "=r"((r)[3]) : "r"(addr))

#define MMA(d, a, b0, b1) \
    asm volatile("mma.sync.aligned.m16n8k16.row.col.f32.f16.f16.f32 " \
                 "{%0,%1,%2,%3}, {%4,%5,%6,%7}, {%8,%9}, {%0,%1,%2,%3};" \
                 : "+f"((d)[0]), "+f"((d)[1]), "+f"((d)[2]), "+f"((d)[3]) \
                 : "r"((a)[0]), "r"((a)[1]), "r"((a)[2]), "r"((a)[3]), "r"(b0), "r"(b1))

#define CPASYNC16(dst, src) \
    asm volatile("cp.async.cg.shared.global [%0], [%1], 16;" :: "r"(dst), "l"(src) : "memory")
#define CP_COMMIT()  asm volatile("cp.async.commit_group;" ::: "memory")
#define CP_WAIT0()   asm volatile("cp.async.wait_group 0;" ::: "memory")

// ---- pre-kernel: bake C into mma B-fragment order (hi/lo fp16 split) ----
__global__ void cc_frag_kernel(const float* __restrict__ cc) {
    int kh = blockIdx.x / 14, n8 = blockIdx.x % 14;
    int l = threadIdx.x;
    int n  = n8 * 8 + (l >> 2);
    int k0 = kh * 16 + (l & 3) * 2;
    uint32_t b0h, b0l, b1h, b1l;
    splith(cc[n * D_DIM + k0],     cc[n * D_DIM + k0 + 1], b0h, b0l);
    splith(cc[n * D_DIM + k0 + 8], cc[n * D_DIM + k0 + 9], b1h, b1l);
    g_bfrag[((kh * 2 + 0) * 14 + n8) * 32 + l] = make_uint2(b0h, b1h);
    g_bfrag[((kh * 2 + 1) * 14 + n8) * 32 + l] = make_uint2(b0l, b1l);
}

__global__ __launch_bounds__(NTHR, 2)
void tse_hmma4_kernel(const float* __restrict__ x,
                      const float* __restrict__ cc,
                      float* __restrict__ out)
{
    extern __shared__ unsigned char smem[];
    const uint32_t sb = smem_u32(smem);
    const int tid = threadIdx.x;
    const int w   = tid >> 5;
    const int l   = tid & 31;
    const int mg  = w & 3;          // rows mg*32 .. mg*32+31
    const int nh  = w >> 2;         // cols nh*56 .. nh*56+55
    const int nb7 = nh * 7;
    const int row0 = blockIdx.x * BM;

    float d[2][7][4];
    #pragma unroll
    for (int m = 0; m < 2; m++)
        #pragma unroll
        for (int p = 0; p < 7; p++)
            #pragma unroll
            for (int j = 0; j < 4; j++) d[m][p][j] = 0.0f;

    const uint32_t aOff = (uint32_t)(mg * 32 + (l & 15)) * A_STRIDE + ((l >> 4) << 4);

    // x staging: 4 float4 per thread per iteration
    const int srow0 = tid >> 3;
    const int sseg  = tid & 7;
    float4 px[4];

    auto FETCH = [&](int it) {
        #pragma unroll
        for (int i = 0; i < 4; i++)
            px[i] = *(const float4*)&x[(size_t)(row0 + srow0 + 32 * i) * D_DIM + it * 32 + sseg * 4];
    };
    auto STOREA = [&](int s) {
        unsigned char* st = smem + s * A_STAGE;
        #pragma unroll
        for (int i = 0; i < 4; i++) {
            uint32_t h0, l0, h1, l1;
            splith(px[i].x, px[i].y, h0, l0);
            splith(px[i].z, px[i].w, h1, l1);
            uint32_t off = (uint32_t)(srow0 + 32 * i) * A_STRIDE + sseg * 8;
            *(uint2*)(st + off)          = make_uint2(h0, h1);
            *(uint2*)(st + A_HALF + off) = make_uint2(l0, l1);
        }
    };
    auto CPB = [&](int it) {          // async-copy B fragments for iteration `it`
        const char* src = (const char*)g_bfrag + (size_t)it * B_STAGE;
        uint32_t dst = sb + B_OFF + (it & 1) * B_STAGE;
        #pragma unroll
        for (int i = 0; i < 4; i++) {
            int idx = tid + 256 * i;                 // 896 x 16B total
            if (i < 3 || idx < 896)
                CPASYNC16(dst + idx * 16, src + idx * 16);
        }
        CP_COMMIT();
    };

    // prologue
    CPB(0);
    FETCH(0);
    STOREA(0);

    for (int it = 0; it < NIT; it++) {
        CP_WAIT0();                         // B(it) arrived (this thread's part)
        __syncthreads();                    // all B(it) copies + A(it) stores visible
        if (it + 1 < NIT) CPB(it + 1);      // prefetch next B one full compute ahead
        if (it + 1 < NIT) FETCH(it + 1);

        const uint32_t aBase = sb + (it & 1) * A_STAGE + aOff;
        const uint2* Bst = (const uint2*)(smem + B_OFF + (it & 1) * B_STAGE);

        #pragma unroll
        for (int h = 0; h < 2; h++) {
            uint32_t ah[2][4], al[2][4];
            LDSM4(ah[0], aBase + h * 32);
            LDSM4(ah[1], aBase + 16 * A_STRIDE + h * 32);
            LDSM4(al[0], aBase + A_HALF + h * 32);
            LDSM4(al[1], aBase + A_HALF + 16 * A_STRIDE + h * 32);

            uint2 b[7];
            #pragma unroll
            for (int p = 0; p < 7; p++)
                b[p] = Bst[((h * 2 + 0) * 14 + nb7 + p) * 32 + l];   // hi frags
            #pragma unroll
            for (int p = 0; p < 7; p++) {
                MMA(d[0][p], ah[0], b[p].x, b[p].y);
                MMA(d[1][p], ah[1], b[p].x, b[p].y);
                MMA(d[0][p], al[0], b[p].x, b[p].y);
                MMA(d[1][p], al[1], b[p].x, b[p].y);
            }
            #pragma unroll
            for (int p = 0; p < 7; p++)
                b[p] = Bst[((h * 2 + 1) * 14 + nb7 + p) * 32 + l];   // lo frags
            #pragma unroll
            for (int p = 0; p < 7; p++) {
                MMA(d[0][p], ah[0], b[p].x, b[p].y);
                MMA(d[1][p], ah[1], b[p].x, b[p].y);
            }
        }

        if (it + 1 < NIT) STOREA((it + 1) & 1);   // disjoint from stage being read
    }
    __syncthreads();

    // ---- dump sims to smem (overlays GEMM buffers) ----
    float* sims = (float*)smem;
    {
        int c0 = nh * 56 + (l & 3) * 2;
        #pragma unroll
        for (int m = 0; m < 2; m++) {
            int r1 = mg * 32 + m * 16 + (l >> 2);
            int r2 = r1 + 8;
            #pragma unroll
            for (int p = 0; p < 7; p++) {
                *(float2*)&sims[r1 * SIMSP + c0 + p * 8] = make_float2(d[m][p][0], d[m][p][1]);
                *(float2*)&sims[r2 * SIMSP + c0 + p * 8] = make_float2(d[m][p][2], d[m][p][3]);
            }
        }
    }
    __syncthreads();

    // ---- per-row top-5 + softmax ----
    float* w5 = (float*)(smem + W5_OFF);
    int*   i5 = (int*)(smem + I5_OFF);
    if (tid < BM) {
        const float* sr = &sims[tid * SIMSP];
        float v0 = -1e30f, v1 = -1e30f, v2 = -1e30f, v3 = -1e30f, v4 = -1e30f;
        int   i0 = 0, i1 = 0, i2 = 0, i3 = 0, i4 = 0;
        for (int c = 0; c < K_DIM; c++) {
            float s = sr[c];
            if (s > v4) {                       // strict >: earliest index wins ties
                v4 = s; i4 = c;
                if (v4 > v3) { float t=v3; v3=v4; v4=t; int q=i3; i3=i4; i4=q; }
                if (v3 > v2) { float t=v2; v2=v3; v3=t; int q=i2; i2=i3; i3=q; }
                if (v2 > v1) { float t=v1; v1=v2; v2=t; int q=i1; i1=i2; i2=q; }
                if (v1 > v0) { float t=v0; v0=v1; v1=t; int q=i0; i0=i1; i1=q; }
            }
        }
        float e1 = __expf(v1 - v0);
        float e2 = __expf(v2 - v0);
        float e3 = __expf(v3 - v0);
        float e4 = __expf(v4 - v0);
        float inv = LAMBDA_ / (1.0f + e1 + e2 + e3 + e4);
        w5[tid*5+0] = inv;      i5[tid*5+0] = i0;
        w5[tid*5+1] = e1 * inv; i5[tid*5+1] = i1;
        w5[tid*5+2] = e2 * inv; i5[tid*5+2] = i2;
        w5[tid*5+3] = e3 * inv; i5[tid*5+3] = i3;
        w5[tid*5+4] = e4 * inv; i5[tid*5+4] = i4;
    }
    __syncthreads();

    // ---- epilogue: warp-per-row, fully coalesced ----
    #pragma unroll 1
    for (int rr = 0; rr < 16; rr++) {
        int r = w * 16 + rr;
        float w0 = w5[r*5+0], w1 = w5[r*5+1], w2 = w5[r*5+2], w3 = w5[r*5+3], w4 = w5[r*5+4];
        int   j0 = i5[r*5+0], j1 = i5[r*5+1], j2 = i5[r*5+2], j3 = i5[r*5+3], j4 = i5[r*5+4];

        const float4* xp = (const float4*)&x[(size_t)(row0 + r) * D_DIM];
        float4*       op = (float4*)&out[(size_t)(row0 + r) * D_DIM];
        const float4* c0 = (const float4*)&cc[(size_t)j0 * D_DIM];
        const float4* c1 = (const float4*)&cc[(size_t)j1 * D_DIM];
        const float4* c2 = (const float4*)&cc[(size_t)j2 * D_DIM];
        const float4* c3 = (const float4*)&cc[(size_t)j3 * D_DIM];
        const float4* c4 = (const float4*)&cc[(size_t)j4 * D_DIM];

        #pragma unroll
        for (int i = 0; i < 4; i++) {
            int q = l + 32 * i;
            float4 xv = xp[q];
            float4 a0 = c0[q], a1 = c1[q], a2 = c2[q], a3 = c3[q], a4 = c4[q];
            float4 o;
            o.x = xv.x + w0*a0.x + w1*a1.x + w2*a2.x + w3*a3.x + w4*a4.x;
            o.y = xv.y + w0*a0.y + w1*a1.y + w2*a2.y + w3*a3.y + w4*a4.y;
            o.z = xv.z + w0*a0.z + w1*a1.z + w2*a2.z + w3*a3.z + w4*a4.z;
            o.w = xv.w + w0*a0.w + w1*a1.w + w2*a2.w + w3*a3.w + w4*a4.w;
            op[q] = o;
        }
    }
}

extern "C" void kernel_launch(void* const* d_in, const int* in_sizes, int n_in,
                              void* d_out, int out_size)
{
    const float* x  = (const float*)d_in[0];
    const float* cc = (const float*)d_in[1];
    int B = in_sizes[0] / D_DIM;

    cc_frag_kernel<<<32 * 14, 32>>>(cc);

    cudaFuncSetAttribute(tse_hmma4_kernel, cudaFuncAttributeMaxDynamicSharedMemorySize, SMEM_BYTES);
    tse_hmma4_kernel<<<B / BM, NTHR, SMEM_BYTES>>>(x, cc, (float*)d_out);
}